// round 3
// baseline (speedup 1.0000x reference)
#include <cuda_runtime.h>

#define BB   32
#define NN   1024
#define WW_  128
#define RR   4
#define SEQ  512
#define DIN  512
#define IFACE 919

// Flattened output offsets (tuple concat order: out, memory, link, usage, prec, ww, rw)
#define OUT_OFF    0ull
#define MEM_OFF    16384ull
#define LINK_OFF   4210688ull
#define USAGE_OFF  37765120ull
#define PREC_OFF   37797888ull
#define WWO_OFF    37830656ull
#define RW_OFF     37863424ull
#define LINK_F4    8388608ull      // 33,554,432 floats / 4

// Zero work-stealing: 4096 chunks of 2048 float4 (32KB) each
#define ZCHUNK_F4  2048
#define NZCHUNK    4096

// Scratch (no allocations allowed)
__device__ float g_part[16 * BB * DIN];
__device__ float g_er[BB * WW_];
__device__ float g_wv[BB * WW_];
__device__ float g_q[BB * RR];
__device__ float g_u[BB];
__device__ int   g_done_mean;
__device__ int   g_flag[BB];
__device__ unsigned int g_zero_ctr;

__device__ __forceinline__ float sigmoidf(float x) {
    return 1.0f / (1.0f + expf(-x));
}

// Reset per-replay state (device globals persist across graph replays)
__global__ void k_init() {
    int t = threadIdx.x;
    if (t == 0) { g_done_mean = 0; g_zero_ctr = 0; }
    if (t < BB) g_flag[t] = 0;
}

// ---------------------------------------------------------------------------
// Fused mega-kernel: grid 592 (148 SMs x 4 -> all co-resident), block 256.
// Roles:
//   bid   0..255 : mean partials of x, then zero-steal
//   bid 256..287 : per-batch compute (combine mean, iface GEMM, activations,
//                  out/ww/prec writes), then zero-steal
//   bid 288..415 : per-batch memory/rw/usage fill (4 blocks per batch),
//                  then zero-steal
//   bid 416..591 : pure zero-steal of the 134MB link region
// ---------------------------------------------------------------------------
__global__ void __launch_bounds__(256, 4)
k_fused(const float* __restrict__ x, const float* __restrict__ Wm,
        float* __restrict__ out) {
    int bid = blockIdx.x, t = threadIdx.x;
    __shared__ float mx[DIN];
    __shared__ float s_rm1[RR], s_fg[RR], s_q[RR];
    __shared__ float s_pw[16];
    __shared__ float s_c1, s_c2;

    if (bid < 256) {
        // ----- mean partial role -----
        int b = bid >> 3, c = bid & 7;
        int col = t & 127;
        int h   = t >> 7;
        const float4* xp = (const float4*)(x + (size_t)b * SEQ * DIN);
        float4 acc = make_float4(0.f, 0.f, 0.f, 0.f);
        int s0 = c * 64 + h * 32;
#pragma unroll 4
        for (int s = s0; s < s0 + 32; s++) {
            float4 v = xp[s * 128 + col];
            acc.x += v.x; acc.y += v.y; acc.z += v.z; acc.w += v.w;
        }
        ((float4*)g_part)[((c * 2 + h) * BB + b) * 128 + col] = acc;
        __syncthreads();
        if (t == 0) { __threadfence(); atomicAdd(&g_done_mean, 1); }
    } else if (bid < 288) {
        // ----- compute role (one block per batch) -----
        int b = bid - 256;
        if (t == 0) { while (atomicAdd(&g_done_mean, 0) < 256) { } __threadfence(); }
        __syncthreads();

        // combine 16 partial chunks -> mean vector in smem
        for (int i = t; i < DIN; i += 256) {
            float s = 0.f;
#pragma unroll
            for (int c = 0; c < 16; c++) s += g_part[(c * BB + b) * DIN + i];
            mx[i] = s * (1.0f / 512.0f);
        }
        __syncthreads();

        // iface = mean @ W for the slots we actually need (all 919 for simplicity
        // is wasteful; we only need 645..918). Compute j in [645, 919).
        // Each thread handles j = 645 + t (274 slots; threads 274..255? t<256 so
        // loop twice with stride 256).
        float f_loc[2];
        int   j_loc[2];
        int nj = 0;
        for (int j = 645 + t; j < IFACE; j += 256) {
            float acc = 0.f;
#pragma unroll 8
            for (int k = 0; k < DIN; k++) acc = fmaf(mx[k], Wm[k * IFACE + j], acc);
            f_loc[nj] = acc; j_loc[nj] = j; nj++;
        }
        __syncthreads();
        // scatter needed iface values into smem (reuse mx region: slots 0..273)
        for (int i = 0; i < nj; i++) mx[j_loc[i] - 645] = f_loc[i];
        __syncthreads();
        // mx[0..127]=erase raw, mx[128..255]=write_vector, mx[256..259]=free gates,
        // mx[260]=alloc gate, mx[261]=write gate, mx[262..273]=read modes
        if (t < 128) {
            g_er[b * WW_ + t] = sigmoidf(mx[t]);
            g_wv[b * WW_ + t] = mx[128 + t];
        }
        if (t < RR) {
            float m0 = mx[262 + t], m1 = mx[266 + t], m2 = mx[270 + t];
            float mmax = fmaxf(m0, fmaxf(m1, m2));
            float e0 = expf(m0 - mmax), e1 = expf(m1 - mmax), e2 = expf(m2 - mmax);
            float rm1 = e1 / (e0 + e1 + e2);
            s_rm1[t] = rm1;
            float q = rm1 * (1.0f / 1024.0f);
            s_q[t] = q;
            g_q[b * RR + t] = q;
            s_fg[t] = sigmoidf(mx[256 + t]);
        }
        __syncthreads();
        if (t == 0) {
            float ret = 1.0f;
#pragma unroll
            for (int r = 0; r < RR; r++) ret *= (1.0f - s_fg[r] * s_q[r]);
            float u = 1e-6f * ret;
            g_u[b] = u;
            float ag = sigmoidf(mx[260]);
            float wg = sigmoidf(mx[261]);
            s_c1 = wg * ag * (1.0f - u);
            s_c2 = wg * (1.0f - ag) * (1.0f / 1024.0f);
            float sh = 1.0f;
#pragma unroll
            for (int i = 0; i < 16; i++) { s_pw[i] = sh; sh *= u; }
        }
        __syncthreads();
        // out section: out[b, w*4+r] = 1e-6 * rm1[r]
        if (t < 128) {
            float4 ov = make_float4(1e-6f * s_rm1[0], 1e-6f * s_rm1[1],
                                    1e-6f * s_rm1[2], 1e-6f * s_rm1[3]);
            ((float4*)(out + OUT_OFF))[b * 128 + t] = ov;
        }
        // ww / prec sections
        float c1 = s_c1, c2 = s_c2;
#pragma unroll
        for (int n = t; n < NN; n += 256) {
            float shifted = (n < 16) ? s_pw[n] : 0.0f;
            float ww = fmaf(c1, shifted, c2);
            out[WWO_OFF + (size_t)b * NN + n]  = ww;
            out[PREC_OFF + (size_t)b * NN + n] = ww;
        }
        __syncthreads();
        if (t == 0) { __threadfence(); atomicExch(&g_flag[b], 1); }
    } else if (bid < 416) {
        // ----- fill role: 4 blocks per batch -----
        int r  = bid - 288;
        int b  = r >> 2;
        int q  = r & 3;
        if (t == 0) { while (atomicAdd(&g_flag[b], 0) == 0) { } __threadfence(); }
        __syncthreads();

        // memory quarter: 8192 float4
        int v0 = b * 32768 + q * 8192;
#pragma unroll 4
        for (int i = 0; i < 32; i++) {
            int v = v0 + i * 256 + t;
            int rem = v & 32767;
            int n  = rem >> 5;
            int w4 = rem & 31;
            float ww = __ldg(out + WWO_OFF + (size_t)b * NN + n);
            float4 e  = ((const float4*)g_er)[b * 32 + w4];
            float4 wv = ((const float4*)g_wv)[b * 32 + w4];
            float4 m;
            m.x = 1e-6f * (1.0f - ww * e.x) + ww * wv.x;
            m.y = 1e-6f * (1.0f - ww * e.y) + ww * wv.y;
            m.z = 1e-6f * (1.0f - ww * e.z) + ww * wv.z;
            m.w = 1e-6f * (1.0f - ww * e.w) + ww * wv.w;
            ((float4*)(out + MEM_OFF))[v] = m;
        }
        // rw quarter: 256 float4 ; usage quarter: 256 floats
        {
            int n = q * 256 + t;
            ((float4*)(out + RW_OFF))[b * 1024 + n] = ((const float4*)g_q)[b];
            out[USAGE_OFF + (size_t)b * NN + n] = g_u[b];
        }
    }
    // ----- all blocks: steal zero chunks of the link region -----
    {
        __shared__ unsigned int s_chunk;
        float4 z = make_float4(0.f, 0.f, 0.f, 0.f);
        float4* p = (float4*)(out + LINK_OFF);
        for (;;) {
            if (t == 0) s_chunk = atomicAdd(&g_zero_ctr, 1u);
            __syncthreads();
            unsigned int c = s_chunk;
            __syncthreads();
            if (c >= NZCHUNK) break;
            size_t base = (size_t)c * ZCHUNK_F4;
#pragma unroll
            for (int i = 0; i < 8; i++)
                p[base + i * 256 + t] = z;
        }
    }
}

extern "C" void kernel_launch(void* const* d_in, const int* in_sizes, int n_in,
                              void* d_out, int out_size) {
    const float* x  = (const float*)d_in[0];
    const float* Wm = (const float*)d_in[1];
    float* out = (float*)d_out;

    k_init<<<1, 64>>>();
    k_fused<<<592, 256>>>(x, Wm, out);
}

// round 4
// speedup vs baseline: 1.1233x; 1.1233x over previous
#include <cuda_runtime.h>

#if defined(CUDA_API_PER_THREAD_DEFAULT_STREAM) || defined(__CUDA_API_PER_THREAD_DEFAULT_STREAM)
#define MAIN_STREAM cudaStreamPerThread
#else
#define MAIN_STREAM cudaStreamLegacy
#endif

#define BB   32
#define NN   1024
#define WW_  128
#define RR   4
#define SEQ  512
#define DIN  512
#define IFACE 919

// Flattened output offsets (tuple concat order: out, memory, link, usage, prec, ww, rw)
#define OUT_OFF    0ull
#define MEM_OFF    16384ull
#define LINK_OFF   4210688ull
#define USAGE_OFF  37765120ull
#define PREC_OFF   37797888ull
#define WWO_OFF    37830656ull
#define RW_OFF     37863424ull
#define LINK_BYTES (33554432ull * 4ull)   // 134 MB of zeros

// Scratch (no allocations allowed)
__device__ float g_part[16 * BB * DIN];
__device__ float g_er[BB * WW_];
__device__ float g_wv[BB * WW_];
__device__ float g_q[BB * RR];
__device__ float g_u[BB];

__device__ __forceinline__ float sigmoidf(float x) {
    return 1.0f / (1.0f + expf(-x));
}

// ---------------------------------------------------------------------------
// kA: partial mean of x over seq. grid 256, block 256.
// block (b,c): c-th 64-row chunk of batch b; two 32-row halves across threads.
// ---------------------------------------------------------------------------
__global__ void kA_mean(const float* __restrict__ x) {
    int bid = blockIdx.x, t = threadIdx.x;
    int b = bid >> 3, c = bid & 7;
    int col = t & 127;
    int h   = t >> 7;
    const float4* xp = (const float4*)(x + (size_t)b * SEQ * DIN);
    float4 acc = make_float4(0.f, 0.f, 0.f, 0.f);
    int s0 = c * 64 + h * 32;
#pragma unroll 4
    for (int s = s0; s < s0 + 32; s++) {
        float4 v = xp[s * 128 + col];
        acc.x += v.x; acc.y += v.y; acc.z += v.z; acc.w += v.w;
    }
    ((float4*)g_part)[((c * 2 + h) * BB + b) * 128 + col] = acc;
}

// ---------------------------------------------------------------------------
// kB: one block per batch. Combine partials -> mean (smem), compute only the
// needed iface columns [645,919), activations, and write out/ww/prec.
// ---------------------------------------------------------------------------
__global__ void __launch_bounds__(256)
kB_batch(const float* __restrict__ Wm, float* __restrict__ out) {
    int b = blockIdx.x, t = threadIdx.x;
    __shared__ float mx[DIN];
    __shared__ float s_rm1[RR], s_fg[RR], s_q[RR];
    __shared__ float s_pw[16];
    __shared__ float s_c1, s_c2;

    // combine 16 partial chunks -> mean vector in smem
    for (int i = t; i < DIN; i += 256) {
        float s = 0.f;
#pragma unroll
        for (int c = 0; c < 16; c++) s += g_part[(c * BB + b) * DIN + i];
        mx[i] = s * (1.0f / 512.0f);
    }
    __syncthreads();

    // iface[j] = mean . W[:,j] for j in [645, 919)  (only slots we need)
    float f_loc[2];
    int   j_loc[2];
    int nj = 0;
    for (int j = 645 + t; j < IFACE; j += 256) {
        float acc = 0.f;
#pragma unroll 8
        for (int k = 0; k < DIN; k++) acc = fmaf(mx[k], Wm[k * IFACE + j], acc);
        f_loc[nj] = acc; j_loc[nj] = j; nj++;
    }
    __syncthreads();
    // scatter: mx[0..127]=erase raw, [128..255]=write_vec, [256..259]=free gates,
    // [260]=alloc gate, [261]=write gate, [262..273]=read modes
    for (int i = 0; i < nj; i++) mx[j_loc[i] - 645] = f_loc[i];
    __syncthreads();

    if (t < 128) {
        g_er[b * WW_ + t] = sigmoidf(mx[t]);
        g_wv[b * WW_ + t] = mx[128 + t];
    }
    if (t < RR) {
        float m0 = mx[262 + t], m1 = mx[266 + t], m2 = mx[270 + t];
        float mmax = fmaxf(m0, fmaxf(m1, m2));
        float e0 = expf(m0 - mmax), e1 = expf(m1 - mmax), e2 = expf(m2 - mmax);
        float rm1 = e1 / (e0 + e1 + e2);
        s_rm1[t] = rm1;
        float q = rm1 * (1.0f / 1024.0f);   // exact /2^10
        s_q[t] = q;
        g_q[b * RR + t] = q;
        s_fg[t] = sigmoidf(mx[256 + t]);
    }
    __syncthreads();
    if (t == 0) {
        float ret = 1.0f;
#pragma unroll
        for (int r = 0; r < RR; r++) ret *= (1.0f - s_fg[r] * s_q[r]);
        float u = 1e-6f * ret;              // usage (constant over n)
        g_u[b] = u;
        float ag = sigmoidf(mx[260]);
        float wg = sigmoidf(mx[261]);
        s_c1 = wg * ag * (1.0f - u);
        s_c2 = wg * (1.0f - ag) * (1.0f / 1024.0f);
        float sh = 1.0f;                    // exact sequential cumprod prefix
#pragma unroll
        for (int i = 0; i < 16; i++) { s_pw[i] = sh; sh *= u; }
    }
    __syncthreads();

    // out[b, w*4+r] = 1e-6 * rm1[r]
    if (t < 128) {
        float4 ov = make_float4(1e-6f * s_rm1[0], 1e-6f * s_rm1[1],
                                1e-6f * s_rm1[2], 1e-6f * s_rm1[3]);
        ((float4*)(out + OUT_OFF))[b * 128 + t] = ov;
    }
    // ww / prec sections
    float c1 = s_c1, c2 = s_c2;
#pragma unroll
    for (int n = t; n < NN; n += 256) {
        float shifted = (n < 16) ? s_pw[n] : 0.0f;
        float ww = fmaf(c1, shifted, c2);
        out[WWO_OFF + (size_t)b * NN + n]  = ww;
        out[PREC_OFF + (size_t)b * NN + n] = ww;  // prec == ww
    }
}

// ---------------------------------------------------------------------------
// kC: fills. grid 1088, block 256.
//   bid 0..1023   : memory, 4 float4 per thread
//   bid 1024..1055: rw, 4 float4 per thread
//   bid 1056..1087: usage, 4 floats per thread
// ---------------------------------------------------------------------------
__global__ void kC_fill(float* __restrict__ out) {
    int bid = blockIdx.x, t = threadIdx.x;
    if (bid < 1024) {
        int v0 = bid * 1024;
#pragma unroll
        for (int i = 0; i < 4; i++) {
            int v = v0 + i * 256 + t;       // float4 index into memory
            int b = v >> 15;                // 32768 f4 per batch
            int rem = v & 32767;
            int n  = rem >> 5;
            int w4 = rem & 31;
            float ww = __ldg(out + WWO_OFF + (size_t)b * NN + n);
            float4 e  = ((const float4*)g_er)[b * 32 + w4];
            float4 wv = ((const float4*)g_wv)[b * 32 + w4];
            float4 m;
            m.x = 1e-6f * (1.0f - ww * e.x) + ww * wv.x;
            m.y = 1e-6f * (1.0f - ww * e.y) + ww * wv.y;
            m.z = 1e-6f * (1.0f - ww * e.z) + ww * wv.z;
            m.w = 1e-6f * (1.0f - ww * e.w) + ww * wv.w;
            ((float4*)(out + MEM_OFF))[v] = m;
        }
    } else if (bid < 1056) {
        int base = (bid - 1024) * 1024;
#pragma unroll
        for (int i = 0; i < 4; i++) {
            int v = base + i * 256 + t;     // (b,n) index, f4 over r
            ((float4*)(out + RW_OFF))[v] = ((const float4*)g_q)[v >> 10];
        }
    } else {
        int base = (bid - 1056) * 1024;
#pragma unroll
        for (int i = 0; i < 4; i++) {
            int v = base + i * 256 + t;
            out[USAGE_OFF + v] = g_u[v >> 10];
        }
    }
}

extern "C" void kernel_launch(void* const* d_in, const int* in_sizes, int n_in,
                              void* d_out, int out_size) {
    const float* x  = (const float*)d_in[0];
    const float* Wm = (const float*)d_in[1];
    float* out = (float*)d_out;

    // Fork a parallel branch for the 134MB link-zero so it overlaps the
    // mean -> iface -> fill chain inside the captured graph.
    cudaStream_t s2 = 0;
    cudaEvent_t ev0 = 0, ev1 = 0;
    bool ok = (cudaStreamCreateWithFlags(&s2, cudaStreamNonBlocking) == cudaSuccess);
    if (ok) ok = (cudaEventCreateWithFlags(&ev0, cudaEventDisableTiming) == cudaSuccess);
    if (ok) ok = (cudaEventCreateWithFlags(&ev1, cudaEventDisableTiming) == cudaSuccess);
    if (ok) ok = (cudaEventRecord(ev0, MAIN_STREAM) == cudaSuccess);
    if (ok) ok = (cudaStreamWaitEvent(s2, ev0, 0) == cudaSuccess);
    if (ok) ok = (cudaMemsetAsync(out + LINK_OFF, 0, LINK_BYTES, s2) == cudaSuccess);
    if (ok) ok = (cudaEventRecord(ev1, s2) == cudaSuccess);

    if (!ok) {
        // Fallback: sequential zero on the main stream (R2 behavior).
        cudaMemsetAsync(out + LINK_OFF, 0, LINK_BYTES, MAIN_STREAM);
    }

    kA_mean<<<256, 256>>>(x);
    kB_batch<<<BB, 256>>>(Wm, out);
    kC_fill<<<1088, 256>>>(out);

    if (ok) cudaStreamWaitEvent(MAIN_STREAM, ev1, 0);
    // Note: s2/ev0/ev1 intentionally not destroyed here — destroying a forked
    // stream mid-capture invalidates the capture; kernel_launch is only called
    // a handful of times so the leak is bounded.
}